// round 3
// baseline (speedup 1.0000x reference)
#include <cuda_runtime.h>
#include <math.h>

#define NN 8192
#define TPB 256
#define JPT (NN / TPB)   // 32 j's per thread

// Packed per-point data: {theta, tau, cos(theta), sin(theta)}
__device__ __align__(16) float4 g_packed[NN];

__global__ void prep_kernel(const float* __restrict__ theta,
                            const float* __restrict__ tau) {
    int i = blockIdx.x * blockDim.x + threadIdx.x;
    if (i < NN) {
        float t = theta[i];
        float s, c;
        sincosf(t, &s, &c);
        g_packed[i] = make_float4(t, tau[i], c, s);
    }
}

__device__ __forceinline__ float ex2a(float x) {
    float r; asm("ex2.approx.f32 %0, %1;" : "=f"(r) : "f"(x)); return r;
}
__device__ __forceinline__ float sqrta(float x) {
    float r; asm("sqrt.approx.f32 %0, %1;" : "=f"(r) : "f"(x)); return r;
}
__device__ __forceinline__ float rcpa(float x) {
    float r; asm("rcp.approx.f32 %0, %1;" : "=f"(r) : "f"(x)); return r;
}

__device__ __forceinline__ float warp_sum(float v) {
#pragma unroll
    for (int o = 16; o > 0; o >>= 1) v += __shfl_down_sync(0xffffffffu, v, o);
    return v;
}

__global__ void __launch_bounds__(TPB, 4)
row_kernel(float* __restrict__ out_theta,
           float* __restrict__ out_tau,
           float* __restrict__ out_attn) {
    __shared__ float red[6][TPB / 32];
    __shared__ float sm_inv;

    const int i = blockIdx.x;
    const int t = threadIdx.x;

    const float4 pi = g_packed[i];
    const float th_i = pi.x, ta_i = pi.y, c_i = pi.z, s_i = pi.w;

    const float TWO_PI = 6.28318530717958647692f;
    const float CEXP   = -3.60673760222240851f;   // -2.5 * log2(e)
    const float C3TAU  = 0.3f * CEXP;             // tau weight folded into exp2 arg

    float ev[JPT];                                 // scores live in registers
    float sum = 0.f, ax = 0.f, ay = 0.f, at = 0.f, fx = 0.f, fy = 0.f;

#pragma unroll
    for (int k = 0; k < JPT; k++) {
        const int j = t + k * TPB;
        const float4 pj = g_packed[j];

        // angular + tau distance -> exp2 argument
        float ad  = fabsf(th_i - pj.x);
        float dth = fminf(ad, TWO_PI - ad);
        float dta = fabsf(ta_i - pj.y);
        float arg = fmaf(dth, CEXP, dta * C3TAU);
        float e   = ex2a(arg);                    // single MUFU.EX2
        ev[k] = e;

        sum += e;
        ax = fmaf(e, pj.z, ax);
        ay = fmaf(e, pj.w, ay);
        at = fmaf(e, pj.y, at);

        // repulsion: (1/((dth+0.1)^2 * (sqrt(dx^2+dy^2)+1e-8))) * (dx,dy); 0.15 folded at end
        float d  = dth + 0.1f;
        float dx = c_i - pj.z;
        float dy = s_i - pj.w;
        float n2 = fmaf(dx, dx, dy * dy);
        float sn = sqrta(n2);                     // MUFU.SQRT
        float r  = rcpa((d * d) * (sn + 1e-8f));  // MUFU.RCP
        fx = fmaf(r, dx, fx);                     // exact 0 at j==i (dx=dy=0)
        fy = fmaf(r, dy, fy);
    }

    // block reduction of the 6 accumulators
    sum = warp_sum(sum); ax = warp_sum(ax); ay = warp_sum(ay);
    at  = warp_sum(at);  fx = warp_sum(fx); fy = warp_sum(fy);
    const int lane = t & 31, wid = t >> 5;
    if (lane == 0) {
        red[0][wid] = sum; red[1][wid] = ax; red[2][wid] = ay;
        red[3][wid] = at;  red[4][wid] = fx; red[5][wid] = fy;
    }
    __syncthreads();

    if (t == 0) {
        float S = 0.f, AX = 0.f, AY = 0.f, AT = 0.f, FX = 0.f, FY = 0.f;
#pragma unroll
        for (int w = 0; w < TPB / 32; w++) {
            S += red[0][w]; AX += red[1][w]; AY += red[2][w];
            AT += red[3][w]; FX += red[4][w]; FY += red[5][w];
        }
        // remove self contribution: e(i,i) = exp2(0) = 1 exactly
        S  -= 1.0f;
        AX -= c_i;
        AY -= s_i;
        AT -= ta_i;

        const float inv = 1.0f / S;
        const float Rx = fmaf(AX, inv, 0.15f * FX);
        const float Ry = fmaf(AY, inv, 0.15f * FY);
        out_theta[i] = atan2f(Ry, Rx);
        out_tau[i]   = AT * inv;
        sm_inv = inv;
    }
    __syncthreads();

    // normalize in-register and write attn row (coalesced STG.32)
    const float inv = sm_inv;
    float* __restrict__ row = out_attn + (size_t)i * NN;
#pragma unroll
    for (int k = 0; k < JPT; k++) {
        const int j = t + k * TPB;
        float v = ev[k] * inv;
        row[j] = (j == i) ? 0.0f : v;
    }
}

extern "C" void kernel_launch(void* const* d_in, const int* in_sizes, int n_in,
                              void* d_out, int out_size) {
    const float* theta = (const float*)d_in[0];
    const float* tau   = (const float*)d_in[1];
    float* out = (float*)d_out;

    float* out_theta = out;
    float* out_tau   = out + NN;
    float* out_attn  = out + 2 * NN;

    prep_kernel<<<(NN + 255) / 256, 256>>>(theta, tau);
    row_kernel<<<NN, TPB>>>(out_theta, out_tau, out_attn);
}

// round 4
// speedup vs baseline: 1.0973x; 1.0973x over previous
#include <cuda_runtime.h>
#include <math.h>

#define NN 8192
#define TPB 256
#define JPT (NN / TPB)   // 32 j's per thread

// Packed per-point data: {theta, tau, cos(theta), sin(theta)}
__device__ __align__(16) float4 g_packed[NN];

__global__ void prep_kernel(const float* __restrict__ theta,
                            const float* __restrict__ tau) {
    int i = blockIdx.x * blockDim.x + threadIdx.x;
    if (i < NN) {
        float t = theta[i];
        float s, c;
        sincosf(t, &s, &c);
        g_packed[i] = make_float4(t, tau[i], c, s);
    }
}

__device__ __forceinline__ float ex2a(float x) {
    float r; asm("ex2.approx.f32 %0, %1;" : "=f"(r) : "f"(x)); return r;
}
__device__ __forceinline__ float rsqa(float x) {
    float r; asm("rsqrt.approx.f32 %0, %1;" : "=f"(r) : "f"(x)); return r;
}

__device__ __forceinline__ float warp_sum(float v) {
#pragma unroll
    for (int o = 16; o > 0; o >>= 1) v += __shfl_down_sync(0xffffffffu, v, o);
    return v;
}

__global__ void __launch_bounds__(TPB, 6)
row_kernel(float* __restrict__ out_theta,
           float* __restrict__ out_tau,
           float* __restrict__ out_attn) {
    __shared__ __align__(16) float sm_e[NN];     // unnormalized scores for this row
    __shared__ float red[6][TPB / 32];
    __shared__ float sm_inv;

    const int i = blockIdx.x;
    const int t = threadIdx.x;

    const float4 pi = g_packed[i];
    const float th_i = pi.x, ta_i = pi.y, c_i = pi.z, s_i = pi.w;

    const float TWO_PI = 6.28318530717958647692f;
    const float CEXP   = -3.60673760222240851f;   // -2.5 * log2(e)
    const float C3TAU  = 0.3f * CEXP;             // tau weight folded into exp2 arg

    float sum = 0.f, ax = 0.f, ay = 0.f, at = 0.f, fx = 0.f, fy = 0.f;

#pragma unroll 4
    for (int k = 0; k < JPT; k++) {
        const int j = t + k * TPB;
        const float4 pj = g_packed[j];

        // angular + tau distance -> exp2 argument
        float ad   = fabsf(th_i - pj.x);
        float dth  = fminf(ad, TWO_PI - ad);
        float dta  = fabsf(ta_i - pj.y);
        float arg  = fmaf(dth, CEXP, dta * C3TAU);
        float e    = ex2a(arg);                   // single MUFU.EX2

        sum += e;
        ax = fmaf(e, pj.z, ax);
        ay = fmaf(e, pj.w, ay);
        at = fmaf(e, pj.y, at);
        sm_e[j] = e;

        // repulsion: w = 1/sqrt(n2 * d^4) == 1/(d^2 * sqrt(n2)); 0.15 folded at end.
        // +1e-32 keeps j==i finite: rsqrt(1e-32)=1e16, times dx=0 -> exact 0.
        float d    = dth + 0.1f;
        float d2   = d * d;
        float d4   = d2 * d2;
        float dx   = c_i - pj.z;
        float dy   = s_i - pj.w;
        float n2   = fmaf(dx, dx, dy * dy);
        float warg = fmaf(n2, d4, 1e-32f);
        float r    = rsqa(warg);                  // single MUFU.RSQ
        fx = fmaf(r, dx, fx);
        fy = fmaf(r, dy, fy);
    }
    __syncthreads();

    // block reduction of the 6 accumulators
    sum = warp_sum(sum); ax = warp_sum(ax); ay = warp_sum(ay);
    at  = warp_sum(at);  fx = warp_sum(fx); fy = warp_sum(fy);
    const int lane = t & 31, wid = t >> 5;
    if (lane == 0) {
        red[0][wid] = sum; red[1][wid] = ax; red[2][wid] = ay;
        red[3][wid] = at;  red[4][wid] = fx; red[5][wid] = fy;
    }
    __syncthreads();

    if (t == 0) {
        float S = 0.f, AX = 0.f, AY = 0.f, AT = 0.f, FX = 0.f, FY = 0.f;
#pragma unroll
        for (int w = 0; w < TPB / 32; w++) {
            S += red[0][w]; AX += red[1][w]; AY += red[2][w];
            AT += red[3][w]; FX += red[4][w]; FY += red[5][w];
        }
        // remove self contribution: e(i,i) = exp2(0) = 1 exactly; repel self = 0 exactly
        S  -= 1.0f;
        AX -= c_i;
        AY -= s_i;
        AT -= ta_i;

        const float inv = 1.0f / S;
        const float Rx = fmaf(AX, inv, 0.15f * FX);
        const float Ry = fmaf(AY, inv, 0.15f * FY);
        out_theta[i] = atan2f(Ry, Rx);
        out_tau[i]   = AT * inv;
        sm_inv = inv;
        sm_e[i] = 0.0f;      // attn diagonal
    }
    __syncthreads();

    // normalize + write attn row (coalesced float4 stores)
    const float inv = sm_inv;
    float4* attn4 = reinterpret_cast<float4*>(out_attn + (size_t)i * NN);
    const float4* e4 = reinterpret_cast<const float4*>(sm_e);
#pragma unroll
    for (int k = 0; k < JPT / 4; k++) {
        const int idx = t + k * TPB;
        float4 v = e4[idx];
        v.x *= inv; v.y *= inv; v.z *= inv; v.w *= inv;
        attn4[idx] = v;
    }
}

extern "C" void kernel_launch(void* const* d_in, const int* in_sizes, int n_in,
                              void* d_out, int out_size) {
    const float* theta = (const float*)d_in[0];
    const float* tau   = (const float*)d_in[1];
    float* out = (float*)d_out;

    float* out_theta = out;
    float* out_tau   = out + NN;
    float* out_attn  = out + 2 * NN;

    prep_kernel<<<(NN + 255) / 256, 256>>>(theta, tau);
    row_kernel<<<NN, TPB>>>(out_theta, out_tau, out_attn);
}

// round 6
// speedup vs baseline: 1.3046x; 1.1889x over previous
#include <cuda_runtime.h>
#include <cuda_fp16.h>
#include <math.h>

#define NN 8192
#define TPB 256
#define RPB 4                     // rows per CTA
#define JPT (NN / TPB)            // 32 j's per thread

// Packed per-point data: {theta, tau, cos(theta), sin(theta)}
__device__ __align__(16) float4 g_packed[NN];

__global__ void prep_kernel(const float* __restrict__ theta,
                            const float* __restrict__ tau) {
    int i = blockIdx.x * blockDim.x + threadIdx.x;
    if (i < NN) {
        float t = theta[i];
        float s, c;
        sincosf(t, &s, &c);
        g_packed[i] = make_float4(t, tau[i], c, s);
    }
}

__device__ __forceinline__ float ex2a(float x) {
    float r; asm("ex2.approx.f32 %0, %1;" : "=f"(r) : "f"(x)); return r;
}
__device__ __forceinline__ float rsqa(float x) {
    float r; asm("rsqrt.approx.f32 %0, %1;" : "=f"(r) : "f"(x)); return r;
}
__device__ __forceinline__ unsigned pack_h2(float a, float b) {
    unsigned r;
    asm("cvt.rn.f16x2.f32 %0, %2, %1;" : "=r"(r) : "f"(a), "f"(b));  // lo=a, hi=b
    return r;
}

__device__ __forceinline__ float warp_sum(float v) {
#pragma unroll
    for (int o = 16; o > 0; o >>= 1) v += __shfl_down_sync(0xffffffffu, v, o);
    return v;
}

__global__ void __launch_bounds__(TPB, 3)
row_kernel(float* __restrict__ out_theta,
           float* __restrict__ out_tau,
           float* __restrict__ out_attn) {
    // scores: rows packed pairwise as f16x2 (row0|row1, row2|row3)
    __shared__ __align__(16) unsigned sm01[NN];
    __shared__ __align__(16) unsigned sm23[NN];
    __shared__ float red[6 * RPB][TPB / 32];
    __shared__ float sm_inv[RPB];

    const int i0 = blockIdx.x * RPB;
    const int t  = threadIdx.x;

    float th[RPB], ta[RPB], ci[RPB], si[RPB];
#pragma unroll
    for (int r = 0; r < RPB; r++) {
        const float4 p = g_packed[i0 + r];
        th[r] = p.x; ta[r] = p.y; ci[r] = p.z; si[r] = p.w;
    }

    const float TWO_PI = 6.28318530717958647692f;
    const float CEXP   = -3.60673760222240851f;   // -2.5 * log2(e)
    const float C3TAU  = 0.3f * CEXP;

    float sum[RPB], ax[RPB], ay[RPB], at[RPB], fx[RPB], fy[RPB];
#pragma unroll
    for (int r = 0; r < RPB; r++) {
        sum[r] = 0.f; ax[r] = 0.f; ay[r] = 0.f;
        at[r]  = 0.f; fx[r] = 0.f; fy[r] = 0.f;
    }

#pragma unroll 4
    for (int k = 0; k < JPT; k++) {
        const int j = t + k * TPB;
        const float4 pj = g_packed[j];
        float e[RPB];
#pragma unroll
        for (int r = 0; r < RPB; r++) {
            float ad   = fabsf(th[r] - pj.x);
            float dth  = fminf(ad, TWO_PI - ad);
            float dta  = fabsf(ta[r] - pj.y);
            float arg  = fmaf(dth, CEXP, dta * C3TAU);
            float ev   = ex2a(arg);                  // MUFU.EX2
            e[r] = ev;

            sum[r] += ev;
            ax[r] = fmaf(ev, pj.z, ax[r]);
            ay[r] = fmaf(ev, pj.w, ay[r]);
            at[r] = fmaf(ev, pj.y, at[r]);

            // repulsion: w = 1/(d^2*sqrt(n2)) = rsqrt(n2*d^4); +1e-32 keeps j==i exact 0
            float d    = dth + 0.1f;
            float d2   = d * d;
            float d4   = d2 * d2;
            float dx   = ci[r] - pj.z;
            float dy   = si[r] - pj.w;
            float n2   = fmaf(dx, dx, dy * dy);
            float w    = rsqa(fmaf(n2, d4, 1e-32f)); // MUFU.RSQ
            fx[r] = fmaf(w, dx, fx[r]);
            fy[r] = fmaf(w, dy, fy[r]);
        }
        sm01[j] = pack_h2(e[0], e[1]);               // one STS.32 per 2 rows
        sm23[j] = pack_h2(e[2], e[3]);
    }

    // block reduction: 24 quantities
    const int lane = t & 31, wid = t >> 5;
#pragma unroll
    for (int r = 0; r < RPB; r++) {
        float a0 = warp_sum(sum[r]), a1 = warp_sum(ax[r]), a2 = warp_sum(ay[r]);
        float a3 = warp_sum(at[r]),  a4 = warp_sum(fx[r]), a5 = warp_sum(fy[r]);
        if (lane == 0) {
            red[6 * r + 0][wid] = a0; red[6 * r + 1][wid] = a1;
            red[6 * r + 2][wid] = a2; red[6 * r + 3][wid] = a3;
            red[6 * r + 4][wid] = a4; red[6 * r + 5][wid] = a5;
        }
    }
    __syncthreads();

    if (t < RPB) {
        const int r = t;
        float S = 0.f, AX = 0.f, AY = 0.f, AT = 0.f, FX = 0.f, FY = 0.f;
#pragma unroll
        for (int w = 0; w < TPB / 32; w++) {
            S  += red[6 * r + 0][w]; AX += red[6 * r + 1][w];
            AY += red[6 * r + 2][w]; AT += red[6 * r + 3][w];
            FX += red[6 * r + 4][w]; FY += red[6 * r + 5][w];
        }
        // remove exact self contribution: e(i,i)=1, repel(i,i)=0
        S  -= 1.0f;
        AX -= ci[r];
        AY -= si[r];
        AT -= ta[r];

        const float inv = 1.0f / S;
        const float Rx = fmaf(AX, inv, 0.15f * FX);
        const float Ry = fmaf(AY, inv, 0.15f * FY);
        const int i = i0 + r;
        out_theta[i] = atan2f(Ry, Rx);
        out_tau[i]   = AT * inv;
        sm_inv[r] = inv;
        // zero this row's half of the packed diagonal word
        if (r < 2) sm01[i] &= (r & 1) ? 0x0000FFFFu : 0xFFFF0000u;
        else       sm23[i] &= (r & 1) ? 0x0000FFFFu : 0xFFFF0000u;
    }
    __syncthreads();

    // write pass: unpack f16x2 -> two rows at once, coalesced float4 stores
    const float inv0 = sm_inv[0], inv1 = sm_inv[1];
    const float inv2 = sm_inv[2], inv3 = sm_inv[3];
    float4* row0 = reinterpret_cast<float4*>(out_attn + (size_t)(i0 + 0) * NN);
    float4* row1 = reinterpret_cast<float4*>(out_attn + (size_t)(i0 + 1) * NN);
    float4* row2 = reinterpret_cast<float4*>(out_attn + (size_t)(i0 + 2) * NN);
    float4* row3 = reinterpret_cast<float4*>(out_attn + (size_t)(i0 + 3) * NN);
    const uint4* s01 = reinterpret_cast<const uint4*>(sm01);
    const uint4* s23 = reinterpret_cast<const uint4*>(sm23);

#pragma unroll
    for (int k = 0; k < NN / 4 / TPB; k++) {
        const int idx = t + k * TPB;
        {
            uint4 v = s01[idx];
            float2 a = __half22float2(*reinterpret_cast<__half2*>(&v.x));
            float2 b = __half22float2(*reinterpret_cast<__half2*>(&v.y));
            float2 c = __half22float2(*reinterpret_cast<__half2*>(&v.z));
            float2 d = __half22float2(*reinterpret_cast<__half2*>(&v.w));
            row0[idx] = make_float4(a.x * inv0, b.x * inv0, c.x * inv0, d.x * inv0);
            row1[idx] = make_float4(a.y * inv1, b.y * inv1, c.y * inv1, d.y * inv1);
        }
        {
            uint4 v = s23[idx];
            float2 a = __half22float2(*reinterpret_cast<__half2*>(&v.x));
            float2 b = __half22float2(*reinterpret_cast<__half2*>(&v.y));
            float2 c = __half22float2(*reinterpret_cast<__half2*>(&v.z));
            float2 d = __half22float2(*reinterpret_cast<__half2*>(&v.w));
            row2[idx] = make_float4(a.x * inv2, b.x * inv2, c.x * inv2, d.x * inv2);
            row3[idx] = make_float4(a.y * inv3, b.y * inv3, c.y * inv3, d.y * inv3);
        }
    }
}

extern "C" void kernel_launch(void* const* d_in, const int* in_sizes, int n_in,
                              void* d_out, int out_size) {
    const float* theta = (const float*)d_in[0];
    const float* tau   = (const float*)d_in[1];
    float* out = (float*)d_out;

    float* out_theta = out;
    float* out_tau   = out + NN;
    float* out_attn  = out + 2 * NN;

    prep_kernel<<<(NN + 255) / 256, 256>>>(theta, tau);
    row_kernel<<<NN / RPB, TPB>>>(out_theta, out_tau, out_attn);
}